// round 4
// baseline (speedup 1.0000x reference)
#include <cuda_runtime.h>
#include <math.h>

#define Bn 4096
#define Dn 128
#define Cn 512
#define EPSF 1e-5f
#define TOTALF (4096.0f + 512.0f * 1e-5f)

// ---- scratch (device globals; no allocation allowed) ----
__device__ float g_mean[Cn * Dn];
__device__ float g_logprior[Cn];
__device__ float g_bias[Cn];
__device__ float g_pp[128 * Dn * Dn];   // partial Gram sums
__device__ float g_pooled[Dn * Dn];
__device__ float g_prec[Dn * Dn];
__device__ float g_Pz[Bn * Dn];
__device__ float g_zPz[Bn];

// ------------------------------------------------------------------
// K1: per-class means via ballot-scan list building (deterministic,
// ordered identical to segment_sum index order). 512 blocks x 128 thr.
// ------------------------------------------------------------------
__global__ void k_stats(const float* __restrict__ z, const int* __restrict__ y) {
    int c = blockIdx.x, tid = threadIdx.x;
    int lane = tid & 31, warp = tid >> 5;
    __shared__ int list[128];
    __shared__ int wcnt[4];
    __shared__ int nbase;
    if (tid == 0) nbase = 0;
    __syncthreads();
    for (int b0 = 0; b0 < Bn; b0 += 128) {
        int yy = y[b0 + tid];
        bool m = (yy == c);
        unsigned mask = __ballot_sync(0xffffffffu, m);
        if (lane == 0) wcnt[warp] = __popc(mask);
        __syncthreads();                       // wcnt visible; nbase from prev iter visible
        int off = nbase;
#pragma unroll
        for (int w = 0; w < 4; w++) if (w < warp) off += wcnt[w];
        off += __popc(mask & ((1u << lane) - 1u));
        if (m && off < 128) list[off] = b0 + tid;
        int tot = wcnt[0] + wcnt[1] + wcnt[2] + wcnt[3];
        __syncthreads();                       // all reads of old nbase done
        if (tid == 0) nbase += tot;
    }
    __syncthreads();
    int n = nbase;
    float ce = (float)n + EPSF;
    // sum listed rows (coalesced, 2 indep chains for MLP)
    float s0 = 0.f, s1 = 0.f;
    int k = 0;
    for (; k + 1 < n; k += 2) {
        s0 += z[list[k] * Dn + tid];
        s1 += z[list[k + 1] * Dn + tid];
    }
    if (k < n) s0 += z[list[k] * Dn + tid];
    g_mean[c * Dn + tid] = (s0 + s1) / ce;
    if (tid == 0) g_logprior[c] = logf(ce) - logf(TOTALF);
}

// ------------------------------------------------------------------
// K2: fused dz + partial Gram. Block p handles rows [32p, 32p+32).
// 128 blocks x 256 threads; 8x8 scatter tile per thread.
// ------------------------------------------------------------------
__global__ void k_gram_part(const float* __restrict__ z, const int* __restrict__ y) {
    int blk = blockIdx.x;
    int tid = threadIdx.x;
    int ty = tid >> 4, tx = tid & 15;
    __shared__ float srow[32 * 128];
    __shared__ int sy[32];
    if (tid < 32) sy[tid] = y[blk * 32 + tid];
    __syncthreads();
    for (int e = tid; e < 32 * 128; e += 256) {
        int rr = e >> 7, j = e & 127;
        srow[e] = z[blk * 32 * 128 + e] - g_mean[sy[rr] * Dn + j];
    }
    __syncthreads();
    float acc[8][8];
#pragma unroll
    for (int i = 0; i < 8; i++)
#pragma unroll
        for (int j = 0; j < 8; j++) acc[i][j] = 0.f;
    for (int bb = 0; bb < 32; bb++) {
        float rA[8], rB[8];
#pragma unroll
        for (int i = 0; i < 8; i++) rA[i] = srow[bb * 128 + ty * 8 + i];
#pragma unroll
        for (int j = 0; j < 8; j++) rB[j] = srow[bb * 128 + tx + 16 * j];
#pragma unroll
        for (int i = 0; i < 8; i++)
#pragma unroll
            for (int j = 0; j < 8; j++) acc[i][j] += rA[i] * rB[j];
    }
    float* dst = g_pp + blk * (Dn * Dn);
#pragma unroll
    for (int i = 0; i < 8; i++)
#pragma unroll
        for (int j = 0; j < 8; j++)
            dst[(ty * 8 + i) * 128 + tx + 16 * j] = acc[i][j];
}

// ------------------------------------------------------------------
// K3: reduce 128 partials -> pooled. 8 independent accumulators (MLP).
// ------------------------------------------------------------------
__global__ void __launch_bounds__(256) k_gram_red() {
    int idx = blockIdx.x * 256 + threadIdx.x;   // 64 blocks x 256
    float a[8];
#pragma unroll
    for (int u = 0; u < 8; u++) a[u] = 0.f;
#pragma unroll
    for (int p0 = 0; p0 < 128; p0 += 8) {
#pragma unroll
        for (int u = 0; u < 8; u++) a[u] += g_pp[(p0 + u) * (Dn * Dn) + idx];
    }
    float s = ((a[0] + a[1]) + (a[2] + a[3])) + ((a[4] + a[5]) + (a[6] + a[7]));
    int i = idx >> 7, j = idx & 127;
    g_pooled[idx] = s * (1.0f / TOTALF) + (i == j ? EPSF : 0.f);
}

// ------------------------------------------------------------------
// K4: 128x128 SPD inverse, in-register Gauss-Jordan (no pivoting).
// ------------------------------------------------------------------
__global__ void __launch_bounds__(1024) k_invert() {
    int tid = threadIdx.x;
    int row = tid >> 3, grp = tid & 7;
    float r[32];
    if (grp < 4) {
#pragma unroll
        for (int t = 0; t < 32; t++) r[t] = g_pooled[row * 128 + grp * 32 + t];
    } else {
        int cbase = (grp - 4) * 32;
#pragma unroll
        for (int t = 0; t < 32; t++) r[t] = (row == cbase + t) ? 1.f : 0.f;
    }
    __shared__ float s_row[256];
    __shared__ float s_f[128];
    __shared__ float s_piv;

    for (int k = 0; k < 128; k++) {
        int gk = k >> 5;
        bool active = (grp >= gk) && (grp <= gk + 4);
        __syncthreads();
        if (grp == gk) {
            if (row == k) s_piv = r[k & 31];
            else          s_f[row] = r[k & 31];
        }
        if (row == k && active) {
#pragma unroll
            for (int t = 0; t < 32; t++) s_row[grp * 32 + t] = r[t];
        }
        __syncthreads();
        float pinv = 1.0f / s_piv;
        if (row == k) {
            if (active) {
#pragma unroll
                for (int t = 0; t < 32; t++) r[t] *= pinv;
            }
        } else if (active) {
            float cf = s_f[row] * pinv;
#pragma unroll
            for (int t = 0; t < 32; t++) r[t] -= cf * s_row[grp * 32 + t];
        }
    }
    __syncthreads();
    if (grp >= 4) {
#pragma unroll
        for (int t = 0; t < 32; t++)
            g_prec[row * 128 + (grp - 4) * 32 + t] = r[t];
    }
}

// ------------------------------------------------------------------
// K5: q[c] = mean_c^T P mean_c ; bias[c] = logprior[c] - 0.5 q[c]
// 4 independent load chains for MLP.
// ------------------------------------------------------------------
__global__ void k_qbias() {
    int c = blockIdx.x, j = threadIdx.x;
    __shared__ float sm[128];
    __shared__ float sred[128];
    sm[j] = g_mean[c * Dn + j];
    __syncthreads();
    float p0 = 0.f, p1 = 0.f, p2 = 0.f, p3 = 0.f;
#pragma unroll
    for (int d = 0; d < 128; d += 4) {
        p0 += sm[d + 0] * g_prec[(d + 0) * 128 + j];
        p1 += sm[d + 1] * g_prec[(d + 1) * 128 + j];
        p2 += sm[d + 2] * g_prec[(d + 2) * 128 + j];
        p3 += sm[d + 3] * g_prec[(d + 3) * 128 + j];
    }
    sred[j] = ((p0 + p1) + (p2 + p3)) * sm[j];
    __syncthreads();
    for (int s = 64; s > 0; s >>= 1) {
        if (j < s) sred[j] += sred[j + s];
        __syncthreads();
    }
    if (j == 0) g_bias[c] = g_logprior[c] - 0.5f * sred[0];
}

// ------------------------------------------------------------------
// K6: Pz = z @ P (P symmetric), fused zPz[b] = dot(Pz[b], z[b]).
// 256 blocks x 128 threads, 16 z-rows per block.
// ------------------------------------------------------------------
__global__ void k_pz(const float* __restrict__ z) {
    int b0 = blockIdx.x * 16;
    int j = threadIdx.x;
    __shared__ float sP[32 * 128];
    __shared__ float sz[16 * 33];
    float acc[16];
#pragma unroll
    for (int t = 0; t < 16; t++) acc[t] = 0.f;

    for (int d0 = 0; d0 < 128; d0 += 32) {
        __syncthreads();
#pragma unroll
        for (int dd = 0; dd < 32; dd++)
            sP[dd * 128 + j] = g_prec[(d0 + dd) * 128 + j];
        for (int e = j; e < 16 * 32; e += 128) {
            int rr = e >> 5, dd = e & 31;
            sz[rr * 33 + dd] = z[(b0 + rr) * Dn + d0 + dd];
        }
        __syncthreads();
        for (int dd = 0; dd < 32; dd++) {
            float pv = sP[dd * 128 + j];
#pragma unroll
            for (int rr = 0; rr < 16; rr++) acc[rr] += sz[rr * 33 + dd] * pv;
        }
    }
#pragma unroll
    for (int rr = 0; rr < 16; rr++) g_Pz[(b0 + rr) * Dn + j] = acc[rr];

    // fused zPz: sprod[j][rr] layout (pad 17) -> conflict-free
    __shared__ float sprod[128 * 17];
#pragma unroll
    for (int rr = 0; rr < 16; rr++)
        sprod[j * 17 + rr] = acc[rr] * z[(b0 + rr) * Dn + j];
    __syncthreads();
    // 8 threads per row: thread t handles rr = t>>3, partial over j = (t&7)+8m
    {
        int rr = j >> 3, part = j & 7;
        float s = 0.f;
        if (j < 128) {
#pragma unroll
            for (int m = 0; m < 16; m++)
                s += sprod[(part + 8 * m) * 17 + rr];
        }
#pragma unroll
        for (int o = 4; o; o >>= 1) s += __shfl_xor_sync(0xffffffffu, s, o);
        if (part == 0) g_zPz[b0 + rr] = s;
    }
}

// ------------------------------------------------------------------
// K7: out[b,c] = Pz[b].mean[c] + bias[c] - 0.5 zPz[b]
// Tiled 64x64 GEMM, 4x4 register tiles.
// ------------------------------------------------------------------
__global__ void k_out(float* __restrict__ out) {
    int bx = blockIdx.x, by = blockIdx.y;
    int tid = threadIdx.x;
    int tx = tid & 15, ty = tid >> 4;
    __shared__ float sA[32 * 65];
    __shared__ float sB[32 * 65];
    float acc[4][4];
#pragma unroll
    for (int i = 0; i < 4; i++)
#pragma unroll
        for (int j = 0; j < 4; j++) acc[i][j] = 0.f;

    for (int d0 = 0; d0 < 128; d0 += 32) {
        __syncthreads();
        for (int e = tid; e < 2048; e += 256) {
            int rr = e >> 5, dd = e & 31;
            sA[dd * 65 + rr] = g_Pz[(by * 64 + rr) * Dn + d0 + dd];
            sB[dd * 65 + rr] = g_mean[(bx * 64 + rr) * Dn + d0 + dd];
        }
        __syncthreads();
        for (int dd = 0; dd < 32; dd++) {
            float rA[4], rB[4];
#pragma unroll
            for (int i = 0; i < 4; i++) rA[i] = sA[dd * 65 + ty * 4 + i];
#pragma unroll
            for (int j = 0; j < 4; j++) rB[j] = sB[dd * 65 + tx * 4 + j];
#pragma unroll
            for (int i = 0; i < 4; i++)
#pragma unroll
                for (int j = 0; j < 4; j++) acc[i][j] += rA[i] * rB[j];
        }
    }
    float zr[4], bc[4];
#pragma unroll
    for (int i = 0; i < 4; i++) zr[i] = g_zPz[by * 64 + ty * 4 + i];
#pragma unroll
    for (int j = 0; j < 4; j++) bc[j] = g_bias[bx * 64 + tx * 4 + j];
#pragma unroll
    for (int i = 0; i < 4; i++) {
        int rr = by * 64 + ty * 4 + i;
        float4 v;
        v.x = acc[i][0] + bc[0] - 0.5f * zr[i];
        v.y = acc[i][1] + bc[1] - 0.5f * zr[i];
        v.z = acc[i][2] + bc[2] - 0.5f * zr[i];
        v.w = acc[i][3] + bc[3] - 0.5f * zr[i];
        *reinterpret_cast<float4*>(&out[rr * Cn + bx * 64 + tx * 4]) = v;
    }
}

// ------------------------------------------------------------------
extern "C" void kernel_launch(void* const* d_in, const int* in_sizes, int n_in,
                              void* d_out, int out_size) {
    const float* z;
    const int* y;
    if (in_sizes[0] == Bn * Dn) {
        z = (const float*)d_in[0];
        y = (const int*)d_in[1];
    } else {
        z = (const float*)d_in[1];
        y = (const int*)d_in[0];
    }
    float* out = (float*)d_out;

    k_stats<<<Cn, 128>>>(z, y);
    k_gram_part<<<128, 256>>>(z, y);
    k_gram_red<<<64, 256>>>();
    k_invert<<<1, 1024>>>();
    k_qbias<<<Cn, 128>>>();
    k_pz<<<Bn / 16, 128>>>(z);
    k_out<<<dim3(8, 64), 256>>>(out);
}

// round 5
// speedup vs baseline: 2.1096x; 2.1096x over previous
#include <cuda_runtime.h>
#include <math.h>

#define Bn 4096
#define Dn 128
#define Cn 512
#define EPSF 1e-5f
#define TOTALF (4096.0f + 512.0f * 1e-5f)
#define NBLK 148
#define NTHR 1024

// ---- scratch (device globals; no allocation allowed) ----
__device__ float g_mean[Cn * Dn];
__device__ float g_u[Cn * Dn];          // sqrt(n+2eps)*mean rows
__device__ float g_lp[Cn];
__device__ float g_bias[Cn];
__device__ float g_pp[144 * Dn * Dn];   // 128 Z-partials + 16 U-partials
__device__ float g_zred[Dn * Dn];
__device__ float g_pooled[Dn * Dn];
__device__ float g_prec[Dn * Dn];
__device__ float g_Pz[Bn * Dn];
__device__ float g_zPz[Bn];
__device__ unsigned g_barctr = 0;       // monotonic; survives graph replays

// ------------------------------------------------------------------
// Lock-free grid barrier. Safe: grid=148 <= SM count, 1 block/SM
// resources -> all blocks co-resident in wave 1. Counter is monotonic
// (ceil-to-multiple target), so no reset needed across graph replays.
// ------------------------------------------------------------------
__device__ __forceinline__ void gbar() {
    __syncthreads();
    if (threadIdx.x == 0) {
        __threadfence();
        unsigned t = atomicAdd(&g_barctr, 1u) + 1u;
        unsigned tgt = ((t + NBLK - 1u) / NBLK) * NBLK;
        while (*(volatile unsigned*)&g_barctr < tgt) {}
        __threadfence();
    }
    __syncthreads();
}

// ------------------------------------------------------------------
// 32-row Gram partial: dst[i][j] = sum_{bb<32} src[bb][i]*src[bb][j]
// 1024 threads, 4x4 register tile each (32x32 thread grid).
// ------------------------------------------------------------------
__device__ __forceinline__ void gram32(const float4* __restrict__ src4,
                                       float4* __restrict__ dst4,
                                       float* srow) {
    int tid = threadIdx.x;
    float4 v = src4[tid];                 // 1024 float4 = 32 rows x 128
    *(float4*)&srow[tid * 4] = v;
    __syncthreads();
    int tx = tid & 31, ty = tid >> 5;
    float acc[4][4];
#pragma unroll
    for (int i = 0; i < 4; i++)
#pragma unroll
        for (int j = 0; j < 4; j++) acc[i][j] = 0.f;
#pragma unroll 8
    for (int bb = 0; bb < 32; bb++) {
        float4 a = *(const float4*)&srow[bb * 128 + ty * 4];
        float4 b = *(const float4*)&srow[bb * 128 + tx * 4];
        float ra[4] = {a.x, a.y, a.z, a.w};
        float rb[4] = {b.x, b.y, b.z, b.w};
#pragma unroll
        for (int i = 0; i < 4; i++)
#pragma unroll
            for (int j = 0; j < 4; j++) acc[i][j] += ra[i] * rb[j];
    }
#pragma unroll
    for (int i = 0; i < 4; i++)
        dst4[(ty * 4 + i) * 32 + tx] =
            make_float4(acc[i][0], acc[i][1], acc[i][2], acc[i][3]);
}

// ------------------------------------------------------------------
__global__ void __launch_bounds__(NTHR) mega(const float* __restrict__ z,
                                             const int* __restrict__ y,
                                             float* __restrict__ out) {
    __shared__ float sm[8704];
    const int blk = blockIdx.x;
    const int tid = threadIdx.x;
    const int lane = tid & 31, warp = tid >> 5;
    const float4* z4 = (const float4*)z;

    // ================= Phase 0: Z-Gram partials || class stats =====
    if (blk < 128) {
        gram32(&z4[blk * 1024], (float4*)&g_pp[blk * 16384], sm);
    } else if (blk < 144) {
        // warp-per-class stats: class c, scan all labels via ballot
        int c = (blk - 128) * 32 + warp;
        float ax = 0.f, ay = 0.f, az = 0.f, aw = 0.f;
        int n = 0;
        for (int b0 = 0; b0 < Bn; b0 += 128) {
            int l0 = y[b0 + lane];
            int l1 = y[b0 + 32 + lane];
            int l2 = y[b0 + 64 + lane];
            int l3 = y[b0 + 96 + lane];
            unsigned m0 = __ballot_sync(0xffffffffu, l0 == c);
            unsigned m1 = __ballot_sync(0xffffffffu, l1 == c);
            unsigned m2 = __ballot_sync(0xffffffffu, l2 == c);
            unsigned m3 = __ballot_sync(0xffffffffu, l3 == c);
            n += __popc(m0) + __popc(m1) + __popc(m2) + __popc(m3);
            unsigned ms[4] = {m0, m1, m2, m3};
#pragma unroll
            for (int k = 0; k < 4; k++) {
                unsigned m = ms[k];
                int base = b0 + k * 32;
                while (m) {
                    int b = base + __ffs(m) - 1;
                    m &= m - 1u;
                    float4 zv = z4[b * 32 + lane];
                    ax += zv.x; ay += zv.y; az += zv.z; aw += zv.w;
                }
            }
        }
        float ce = (float)n + EPSF;
        float inv = 1.0f / ce;
        float4 m4 = make_float4(ax * inv, ay * inv, az * inv, aw * inv);
        ((float4*)g_mean)[c * 32 + lane] = m4;
        float sw = sqrtf((float)n + 2.0f * EPSF);
        ((float4*)g_u)[c * 32 + lane] =
            make_float4(m4.x * sw, m4.y * sw, m4.z * sw, m4.w * sw);
        if (lane == 0) g_lp[c] = logf(ce) - logf(TOTALF);
    }
    gbar();

    // ========= Phase 1: U-Gram partials || Z-partial reduction =====
    if (blk < 16) {
        gram32(&((const float4*)g_u)[blk * 1024],
               (float4*)&g_pp[(128 + blk) * 16384], sm);
    } else if (blk < 32) {
        int idx = (blk - 16) * 1024 + tid;
        float a[8];
#pragma unroll
        for (int u = 0; u < 8; u++) a[u] = 0.f;
#pragma unroll
        for (int p0 = 0; p0 < 128; p0 += 8)
#pragma unroll
            for (int u = 0; u < 8; u++) a[u] += g_pp[(p0 + u) * 16384 + idx];
        g_zred[idx] = ((a[0] + a[1]) + (a[2] + a[3])) +
                      ((a[4] + a[5]) + (a[6] + a[7]));
    }
    gbar();

    // ===== Phase 2 (block 0 only): pooled + register Gauss-Jordan ==
    if (blk == 0) {
        const float invT = 1.0f / TOTALF;
#pragma unroll
        for (int k = 0; k < 16; k++) {
            int idx = k * 1024 + tid;
            float s = g_zred[idx];
#pragma unroll
            for (int u = 0; u < 16; u++) s -= g_pp[(128 + u) * 16384 + idx];
            int i = idx >> 7, j = idx & 127;
            g_pooled[idx] = s * invT + (i == j ? EPSF : 0.f);
        }
        __syncthreads();

        // 128x128 SPD inverse: 1024 thr, row=tid>>3, grp=tid&7 (32 cols)
        int row = tid >> 3, grp = tid & 7;
        float r[32];
        if (grp < 4) {
#pragma unroll
            for (int t = 0; t < 32; t++) r[t] = g_pooled[row * 128 + grp * 32 + t];
        } else {
            int cb = (grp - 4) * 32;
#pragma unroll
            for (int t = 0; t < 32; t++) r[t] = (row == cb + t) ? 1.f : 0.f;
        }
        float* s_row = sm;        // 256
        float* s_f   = sm + 256;  // 128
        float* s_piv = sm + 384;  // 1
        for (int k = 0; k < 128; k++) {
            int gk = k >> 5;
            bool active = (grp >= gk) && (grp <= gk + 4);
            __syncthreads();
            if (grp == gk) {
                if (row == k) s_piv[0] = r[k & 31];
                else          s_f[row] = r[k & 31];
            }
            if (row == k && active) {
#pragma unroll
                for (int t = 0; t < 32; t++) s_row[grp * 32 + t] = r[t];
            }
            __syncthreads();
            float pinv = 1.0f / s_piv[0];
            if (row == k) {
                if (active) {
#pragma unroll
                    for (int t = 0; t < 32; t++) r[t] *= pinv;
                }
            } else if (active) {
                float cf = s_f[row] * pinv;
#pragma unroll
                for (int t = 0; t < 32; t++) r[t] -= cf * s_row[grp * 32 + t];
            }
        }
        __syncthreads();
        if (grp >= 4) {
#pragma unroll
            for (int t = 0; t < 32; t++)
                g_prec[row * 128 + (grp - 4) * 32 + t] = r[t];
        }
    }
    gbar();

    // ========= Phase 3: Pz + zPz (0-127) || qbias (128-143) ========
    if (blk < 128) {
        int b0 = blk * 32;
        float* szf = sm;            // 32x128
        float* sP  = sm + 4096;     // 32x128
        float* swp = sm + 8192;     // 32x4
        *(float4*)&szf[tid * 4] = z4[b0 * 32 + tid];
        int j = tid & 127, rg = tid >> 7;
        float acc[4] = {0.f, 0.f, 0.f, 0.f};
        for (int d0 = 0; d0 < 128; d0 += 32) {
            __syncthreads();
            ((float4*)sP)[tid] = ((const float4*)g_prec)[d0 * 32 + tid];
            __syncthreads();
#pragma unroll 8
            for (int dd = 0; dd < 32; dd++) {
                float pv = sP[dd * 128 + j];
#pragma unroll
                for (int rr = 0; rr < 4; rr++)
                    acc[rr] += szf[(rg * 4 + rr) * 128 + d0 + dd] * pv;
            }
        }
#pragma unroll
        for (int rr = 0; rr < 4; rr++)
            g_Pz[(b0 + rg * 4 + rr) * 128 + j] = acc[rr];
        // fused zPz
        int jc = (tid >> 5) & 3;
#pragma unroll
        for (int rr = 0; rr < 4; rr++) {
            float s = acc[rr] * szf[(rg * 4 + rr) * 128 + j];
#pragma unroll
            for (int o = 16; o; o >>= 1) s += __shfl_xor_sync(0xffffffffu, s, o);
            if (lane == 0) swp[(rg * 4 + rr) * 4 + jc] = s;
        }
        __syncthreads();
        if (tid < 32)
            g_zPz[b0 + tid] = (swp[tid * 4 + 0] + swp[tid * 4 + 1]) +
                              (swp[tid * 4 + 2] + swp[tid * 4 + 3]);
    } else if (blk < 144) {
        // bias[c] = logprior[c] - 0.5 * m_c^T P m_c   (warp per class)
        int c = (blk - 128) * 32 + warp;
        float4 m4 = ((const float4*)g_mean)[c * 32 + lane];
        float4 v = make_float4(0.f, 0.f, 0.f, 0.f);
        const float4* prec4 = (const float4*)g_prec;
#pragma unroll 4
        for (int d0 = 0; d0 < 128; d0 += 4) {
            int src = d0 >> 2;
            float a0 = __shfl_sync(0xffffffffu, m4.x, src);
            float a1 = __shfl_sync(0xffffffffu, m4.y, src);
            float a2 = __shfl_sync(0xffffffffu, m4.z, src);
            float a3 = __shfl_sync(0xffffffffu, m4.w, src);
            float4 p0 = prec4[(d0 + 0) * 32 + lane];
            float4 p1 = prec4[(d0 + 1) * 32 + lane];
            float4 p2 = prec4[(d0 + 2) * 32 + lane];
            float4 p3 = prec4[(d0 + 3) * 32 + lane];
            v.x += a0 * p0.x + a1 * p1.x + a2 * p2.x + a3 * p3.x;
            v.y += a0 * p0.y + a1 * p1.y + a2 * p2.y + a3 * p3.y;
            v.z += a0 * p0.z + a1 * p1.z + a2 * p2.z + a3 * p3.z;
            v.w += a0 * p0.w + a1 * p1.w + a2 * p2.w + a3 * p3.w;
        }
        float q = v.x * m4.x + v.y * m4.y + v.z * m4.z + v.w * m4.w;
#pragma unroll
        for (int o = 16; o; o >>= 1) q += __shfl_xor_sync(0xffffffffu, q, o);
        if (lane == 0) g_bias[c] = g_lp[c] - 0.5f * q;
    }
    gbar();

    // ===== Phase 4: out = Pz @ mean^T + bias - 0.5 zPz  (0-127) ====
    if (blk < 128) {
        int by = blk >> 2, bx = blk & 3;   // 32 x 4 tiles of 128x128
        float* sA = sm;                    // [32][132] transposed Pz
        float* sB = sm + 32 * 132;         // [32][132] transposed mean
        int tx = tid & 31, ty = tid >> 5;
        float acc[4][4];
#pragma unroll
        for (int i = 0; i < 4; i++)
#pragma unroll
            for (int j = 0; j < 4; j++) acc[i][j] = 0.f;
        for (int d0 = 0; d0 < 128; d0 += 32) {
            __syncthreads();
#pragma unroll
            for (int e0 = 0; e0 < 4096; e0 += 1024) {
                int e = e0 + tid;
                int dd = e & 31, rr = e >> 5;
                sA[dd * 132 + rr] = g_Pz[(by * 128 + rr) * 128 + d0 + dd];
                sB[dd * 132 + rr] = g_mean[(bx * 128 + rr) * 128 + d0 + dd];
            }
            __syncthreads();
#pragma unroll 8
            for (int dd = 0; dd < 32; dd++) {
                float4 a = *(const float4*)&sA[dd * 132 + ty * 4];
                float4 b = *(const float4*)&sB[dd * 132 + tx * 4];
                float ra[4] = {a.x, a.y, a.z, a.w};
                float rb[4] = {b.x, b.y, b.z, b.w};
#pragma unroll
                for (int i = 0; i < 4; i++)
#pragma unroll
                    for (int j = 0; j < 4; j++) acc[i][j] += ra[i] * rb[j];
            }
        }
        float zr[4];
        float4 bc = *(const float4*)&g_bias[bx * 128 + tx * 4];
#pragma unroll
        for (int i = 0; i < 4; i++) zr[i] = g_zPz[by * 128 + ty * 4 + i];
        float bcv[4] = {bc.x, bc.y, bc.z, bc.w};
#pragma unroll
        for (int i = 0; i < 4; i++) {
            int row = by * 128 + ty * 4 + i;
            float4 o;
            o.x = acc[i][0] + bcv[0] - 0.5f * zr[i];
            o.y = acc[i][1] + bcv[1] - 0.5f * zr[i];
            o.z = acc[i][2] + bcv[2] - 0.5f * zr[i];
            o.w = acc[i][3] + bcv[3] - 0.5f * zr[i];
            *(float4*)&out[row * Cn + bx * 128 + tx * 4] = o;
        }
    }
}

// ------------------------------------------------------------------
extern "C" void kernel_launch(void* const* d_in, const int* in_sizes, int n_in,
                              void* d_out, int out_size) {
    const float* z;
    const int* y;
    if (in_sizes[0] == Bn * Dn) {
        z = (const float*)d_in[0];
        y = (const int*)d_in[1];
    } else {
        z = (const float*)d_in[1];
        y = (const int*)d_in[0];
    }
    mega<<<NBLK, NTHR>>>(z, y, (float*)d_out);
}

// round 6
// speedup vs baseline: 4.6413x; 2.2001x over previous
#include <cuda_runtime.h>
#include <math.h>

#define Bn 4096
#define Dn 128
#define Cn 512
#define EPSF 1e-5f
#define TOTALF (4096.0f + 512.0f * 1e-5f)
#define NBLK 148
#define NTHR 1024

// ---- scratch (device globals; no allocation allowed) ----
__device__ float g_mean[Cn * Dn];
__device__ float g_u[Cn * Dn];          // sqrt(n+2eps)*mean rows
__device__ float g_lp[Cn];
__device__ float g_bias[Cn];
__device__ float g_pp[144 * Dn * Dn];   // 128 Z-partials + 16 U-partials
__device__ float g_zred[Dn * Dn];
__device__ float g_pooled[Dn * Dn];
__device__ float g_prec[Dn * Dn];
__device__ float g_Pz[Bn * Dn];
__device__ float g_zPz[Bn];
__device__ unsigned g_barctr = 0;       // monotonic; survives graph replays

// ------------------------------------------------------------------
// Lock-free grid barrier (148 blocks <= SM count -> co-resident).
// Monotonic counter: no reset needed across graph replays.
// ------------------------------------------------------------------
__device__ __forceinline__ void gbar() {
    __syncthreads();
    if (threadIdx.x == 0) {
        __threadfence();
        unsigned t = atomicAdd(&g_barctr, 1u) + 1u;
        unsigned tgt = ((t + NBLK - 1u) / NBLK) * NBLK;
        while (*(volatile unsigned*)&g_barctr < tgt) {}
        __threadfence();
    }
    __syncthreads();
}

// ------------------------------------------------------------------
// 32-row Gram partial: dst[i][j] = sum_{bb<32} src[bb][i]*src[bb][j]
// ------------------------------------------------------------------
__device__ __forceinline__ void gram32(const float4* __restrict__ src4,
                                       float4* __restrict__ dst4,
                                       float* srow) {
    int tid = threadIdx.x;
    float4 v = src4[tid];                 // 1024 float4 = 32 rows x 128
    *(float4*)&srow[tid * 4] = v;
    __syncthreads();
    int tx = tid & 31, ty = tid >> 5;
    float acc[4][4];
#pragma unroll
    for (int i = 0; i < 4; i++)
#pragma unroll
        for (int j = 0; j < 4; j++) acc[i][j] = 0.f;
#pragma unroll 8
    for (int bb = 0; bb < 32; bb++) {
        float4 a = *(const float4*)&srow[bb * 128 + ty * 4];
        float4 b = *(const float4*)&srow[bb * 128 + tx * 4];
        float ra[4] = {a.x, a.y, a.z, a.w};
        float rb[4] = {b.x, b.y, b.z, b.w};
#pragma unroll
        for (int i = 0; i < 4; i++)
#pragma unroll
            for (int j = 0; j < 4; j++) acc[i][j] += ra[i] * rb[j];
    }
#pragma unroll
    for (int i = 0; i < 4; i++)
        dst4[(ty * 4 + i) * 32 + tx] =
            make_float4(acc[i][0], acc[i][1], acc[i][2], acc[i][3]);
}

// ------------------------------------------------------------------
__global__ void __launch_bounds__(NTHR) mega(const float* __restrict__ z,
                                             const int* __restrict__ y,
                                             float* __restrict__ out) {
    __shared__ float sm[8704];
    const int blk = blockIdx.x;
    const int tid = threadIdx.x;
    const int lane = tid & 31, warp = tid >> 5;
    const float4* z4 = (const float4*)z;

    // ================= Phase 0: Z-Gram partials || class stats =====
    if (blk < 128) {
        gram32(&z4[blk * 1024], (float4*)&g_pp[blk * 16384], sm);
    } else if (blk < 144) {
        // warp-per-class stats via ballot scan
        int c = (blk - 128) * 32 + warp;
        float ax = 0.f, ay = 0.f, az = 0.f, aw = 0.f;
        int n = 0;
        for (int b0 = 0; b0 < Bn; b0 += 128) {
            int l0 = y[b0 + lane];
            int l1 = y[b0 + 32 + lane];
            int l2 = y[b0 + 64 + lane];
            int l3 = y[b0 + 96 + lane];
            unsigned m0 = __ballot_sync(0xffffffffu, l0 == c);
            unsigned m1 = __ballot_sync(0xffffffffu, l1 == c);
            unsigned m2 = __ballot_sync(0xffffffffu, l2 == c);
            unsigned m3 = __ballot_sync(0xffffffffu, l3 == c);
            n += __popc(m0) + __popc(m1) + __popc(m2) + __popc(m3);
            unsigned ms[4] = {m0, m1, m2, m3};
#pragma unroll
            for (int k = 0; k < 4; k++) {
                unsigned m = ms[k];
                int base = b0 + k * 32;
                while (m) {
                    int b = base + __ffs(m) - 1;
                    m &= m - 1u;
                    float4 zv = z4[b * 32 + lane];
                    ax += zv.x; ay += zv.y; az += zv.z; aw += zv.w;
                }
            }
        }
        float ce = (float)n + EPSF;
        float inv = 1.0f / ce;
        float4 m4 = make_float4(ax * inv, ay * inv, az * inv, aw * inv);
        ((float4*)g_mean)[c * 32 + lane] = m4;
        float sw = sqrtf((float)n + 2.0f * EPSF);
        ((float4*)g_u)[c * 32 + lane] =
            make_float4(m4.x * sw, m4.y * sw, m4.z * sw, m4.w * sw);
        if (lane == 0) g_lp[c] = logf(ce) - logf(TOTALF);
    }
    gbar();

    // ========= Phase 1: U-Gram partials || Z-partial reduction =====
    if (blk < 16) {
        gram32(&((const float4*)g_u)[blk * 1024],
               (float4*)&g_pp[(128 + blk) * 16384], sm);
    } else if (blk < 32) {
        int idx = (blk - 16) * 1024 + tid;
        float a[8];
#pragma unroll
        for (int u = 0; u < 8; u++) a[u] = 0.f;
#pragma unroll
        for (int p0 = 0; p0 < 128; p0 += 8)
#pragma unroll
            for (int u = 0; u < 8; u++) a[u] += g_pp[(p0 + u) * 16384 + idx];
        g_zred[idx] = ((a[0] + a[1]) + (a[2] + a[3])) +
                      ((a[4] + a[5]) + (a[6] + a[7]));
    }
    gbar();

    // ===== Phase 2 (block 0): pooled + IN-PLACE register GJ inverse =
    // No dynamic register indexing anywhere (pivot column handled via
    // fully-unrolled predicated selects) -> r[16] stays in registers.
    if (blk == 0) {
        const float invT = 1.0f / TOTALF;
#pragma unroll
        for (int k = 0; k < 16; k++) {
            int idx = k * 1024 + tid;
            float s = g_zred[idx];
#pragma unroll
            for (int u = 0; u < 16; u++) s -= g_pp[(128 + u) * 16384 + idx];
            int i = idx >> 7, j = idx & 127;
            g_pooled[idx] = s * invT + (i == j ? EPSF : 0.f);
        }
        __syncthreads();

        // row = tid>>3 (0..127), grp = tid&7, 16 cols each
        const int row = tid >> 3, grp = tid & 7;
        float r[16];
#pragma unroll
        for (int t = 0; t < 16; t += 4) {
            float4 v = *(const float4*)&g_pooled[row * 128 + grp * 16 + t];
            r[t] = v.x; r[t + 1] = v.y; r[t + 2] = v.z; r[t + 3] = v.w;
        }
        // double-buffered shared: s_row2[2][128], s_f2[2][128], s_piv2[2]
        float* s_row2 = sm;            // 256
        float* s_f2   = sm + 256;      // 256
        float* s_piv2 = sm + 512;      // 2

#pragma unroll 1
        for (int k = 0; k < 128; k++) {
            const int p = k & 1;
            const int gk = k >> 4;
            const int kk = k & 15;
            if (grp == gk) {
                float cv = 0.f;
#pragma unroll
                for (int t = 0; t < 16; t++) if (t == kk) cv = r[t];
                if (row == k) s_piv2[p] = cv;
                else          s_f2[p * 128 + row] = cv;
            }
            __syncthreads();
            float pinv = 1.0f / s_piv2[p];
            if (row == k) {
#pragma unroll
                for (int t = 0; t < 16; t++) r[t] *= pinv;
                if (grp == gk) {
#pragma unroll
                    for (int t = 0; t < 16; t++) if (t == kk) r[t] = pinv;
                }
#pragma unroll
                for (int t = 0; t < 16; t++) s_row2[p * 128 + grp * 16 + t] = r[t];
            }
            __syncthreads();
            if (row != k) {
                float f = s_f2[p * 128 + row];
#pragma unroll
                for (int t = 0; t < 16; t++)
                    r[t] -= f * s_row2[p * 128 + grp * 16 + t];
                if (grp == gk) {
                    float nv = -f * pinv;
#pragma unroll
                    for (int t = 0; t < 16; t++) if (t == kk) r[t] = nv;
                }
            }
        }
        __syncthreads();
#pragma unroll
        for (int t = 0; t < 16; t += 4) {
            float4 v = make_float4(r[t], r[t + 1], r[t + 2], r[t + 3]);
            *(float4*)&g_prec[row * 128 + grp * 16 + t] = v;
        }
    }
    gbar();

    // ========= Phase 3: Pz + zPz (0-127) || qbias (128-143) ========
    if (blk < 128) {
        int b0 = blk * 32;
        float* szf = sm;            // 32x128
        float* sP  = sm + 4096;     // 32x128
        float* swp = sm + 8192;     // 32x4
        *(float4*)&szf[tid * 4] = z4[b0 * 32 + tid];
        int j = tid & 127, rg = tid >> 7;
        float acc[4] = {0.f, 0.f, 0.f, 0.f};
        for (int d0 = 0; d0 < 128; d0 += 32) {
            __syncthreads();
            ((float4*)sP)[tid] = ((const float4*)g_prec)[d0 * 32 + tid];
            __syncthreads();
#pragma unroll 8
            for (int dd = 0; dd < 32; dd++) {
                float pv = sP[dd * 128 + j];
#pragma unroll
                for (int rr = 0; rr < 4; rr++)
                    acc[rr] += szf[(rg * 4 + rr) * 128 + d0 + dd] * pv;
            }
        }
#pragma unroll
        for (int rr = 0; rr < 4; rr++)
            g_Pz[(b0 + rg * 4 + rr) * 128 + j] = acc[rr];
        // fused zPz
        int jc = (tid >> 5) & 3;
#pragma unroll
        for (int rr = 0; rr < 4; rr++) {
            float s = acc[rr] * szf[(rg * 4 + rr) * 128 + j];
#pragma unroll
            for (int o = 16; o; o >>= 1) s += __shfl_xor_sync(0xffffffffu, s, o);
            if (lane == 0) swp[(rg * 4 + rr) * 4 + jc] = s;
        }
        __syncthreads();
        if (tid < 32)
            g_zPz[b0 + tid] = (swp[tid * 4 + 0] + swp[tid * 4 + 1]) +
                              (swp[tid * 4 + 2] + swp[tid * 4 + 3]);
    } else if (blk < 144) {
        // bias[c] = logprior[c] - 0.5 * m_c^T P m_c   (warp per class)
        int c = (blk - 128) * 32 + warp;
        float4 m4 = ((const float4*)g_mean)[c * 32 + lane];
        float4 v = make_float4(0.f, 0.f, 0.f, 0.f);
        const float4* prec4 = (const float4*)g_prec;
#pragma unroll 4
        for (int d0 = 0; d0 < 128; d0 += 4) {
            int src = d0 >> 2;
            float a0 = __shfl_sync(0xffffffffu, m4.x, src);
            float a1 = __shfl_sync(0xffffffffu, m4.y, src);
            float a2 = __shfl_sync(0xffffffffu, m4.z, src);
            float a3 = __shfl_sync(0xffffffffu, m4.w, src);
            float4 p0 = prec4[(d0 + 0) * 32 + lane];
            float4 p1 = prec4[(d0 + 1) * 32 + lane];
            float4 p2 = prec4[(d0 + 2) * 32 + lane];
            float4 p3 = prec4[(d0 + 3) * 32 + lane];
            v.x += a0 * p0.x + a1 * p1.x + a2 * p2.x + a3 * p3.x;
            v.y += a0 * p0.y + a1 * p1.y + a2 * p2.y + a3 * p3.y;
            v.z += a0 * p0.z + a1 * p1.z + a2 * p2.z + a3 * p3.z;
            v.w += a0 * p0.w + a1 * p1.w + a2 * p2.w + a3 * p3.w;
        }
        float q = v.x * m4.x + v.y * m4.y + v.z * m4.z + v.w * m4.w;
#pragma unroll
        for (int o = 16; o; o >>= 1) q += __shfl_xor_sync(0xffffffffu, q, o);
        if (lane == 0) g_bias[c] = g_lp[c] - 0.5f * q;
    }
    gbar();

    // ===== Phase 4: out = Pz @ mean^T + bias - 0.5 zPz  (0-127) ====
    if (blk < 128) {
        int by = blk >> 2, bx = blk & 3;   // 32 x 4 tiles of 128x128
        float* sA = sm;                    // [32][132] transposed Pz
        float* sB = sm + 32 * 132;         // [32][132] transposed mean
        int tx = tid & 31, ty = tid >> 5;
        float acc[4][4];
#pragma unroll
        for (int i = 0; i < 4; i++)
#pragma unroll
            for (int j = 0; j < 4; j++) acc[i][j] = 0.f;
        for (int d0 = 0; d0 < 128; d0 += 32) {
            __syncthreads();
#pragma unroll
            for (int e0 = 0; e0 < 4096; e0 += 1024) {
                int e = e0 + tid;
                int dd = e & 31, rr = e >> 5;
                sA[dd * 132 + rr] = g_Pz[(by * 128 + rr) * 128 + d0 + dd];
                sB[dd * 132 + rr] = g_mean[(bx * 128 + rr) * 128 + d0 + dd];
            }
            __syncthreads();
#pragma unroll 8
            for (int dd = 0; dd < 32; dd++) {
                float4 a = *(const float4*)&sA[dd * 132 + ty * 4];
                float4 b = *(const float4*)&sB[dd * 132 + tx * 4];
                float ra[4] = {a.x, a.y, a.z, a.w};
                float rb[4] = {b.x, b.y, b.z, b.w};
#pragma unroll
                for (int i = 0; i < 4; i++)
#pragma unroll
                    for (int j = 0; j < 4; j++) acc[i][j] += ra[i] * rb[j];
            }
        }
        float zr[4];
        float4 bc = *(const float4*)&g_bias[bx * 128 + tx * 4];
#pragma unroll
        for (int i = 0; i < 4; i++) zr[i] = g_zPz[by * 128 + ty * 4 + i];
        float bcv[4] = {bc.x, bc.y, bc.z, bc.w};
#pragma unroll
        for (int i = 0; i < 4; i++) {
            int row = by * 128 + ty * 4 + i;
            float4 o;
            o.x = acc[i][0] + bcv[0] - 0.5f * zr[i];
            o.y = acc[i][1] + bcv[1] - 0.5f * zr[i];
            o.z = acc[i][2] + bcv[2] - 0.5f * zr[i];
            o.w = acc[i][3] + bcv[3] - 0.5f * zr[i];
            *(float4*)&out[row * Cn + bx * 128 + tx * 4] = o;
        }
    }
}

// ------------------------------------------------------------------
extern "C" void kernel_launch(void* const* d_in, const int* in_sizes, int n_in,
                              void* d_out, int out_size) {
    const float* z;
    const int* y;
    if (in_sizes[0] == Bn * Dn) {
        z = (const float*)d_in[0];
        y = (const int*)d_in[1];
    } else {
        z = (const float*)d_in[1];
        y = (const int*)d_in[0];
    }
    mega<<<NBLK, NTHR>>>(z, y, (float*)d_out);
}

// round 8
// speedup vs baseline: 4.8359x; 1.0419x over previous
#include <cuda_runtime.h>
#include <math.h>

#define Bn 4096
#define Dn 128
#define Cn 512
#define EPSF 1e-5f
#define TOTALF (4096.0f + 512.0f * 1e-5f)
#define NBLK 148
#define NTHR 1024

// ---- scratch (device globals; no allocation allowed) ----
__device__ float g_mean[Cn * Dn];
__device__ float g_u[Cn * Dn];          // sqrt(n+2eps)*mean rows
__device__ float g_lp[Cn];
__device__ float g_bias[Cn];
__device__ float g_pp[144 * Dn * Dn];   // 128 Z-partials + 16 U-partials
__device__ float g_pooled[Dn * Dn];
__device__ float g_prec[Dn * Dn];
__device__ float g_Pz[Bn * Dn];
__device__ float g_zPz[Bn];
__device__ unsigned g_barctr = 0;       // monotonic; survives graph replays

// ------------------------------------------------------------------
// Lock-free grid barrier (all kernels use grid=148 <= SM count).
// Monotonic counter: no reset needed across kernels or graph replays.
// ------------------------------------------------------------------
__device__ __forceinline__ void gbar() {
    __syncthreads();
    if (threadIdx.x == 0) {
        __threadfence();
        unsigned t = atomicAdd(&g_barctr, 1u) + 1u;
        unsigned tgt = ((t + NBLK - 1u) / NBLK) * NBLK;
        while (*(volatile unsigned*)&g_barctr < tgt) {}
        __threadfence();
    }
    __syncthreads();
}

// ------------------------------------------------------------------
// 32-row Gram partial: dst[i][j] = sum_{bb<32} src[bb][i]*src[bb][j]
// ------------------------------------------------------------------
__device__ __forceinline__ void gram32(const float4* __restrict__ src4,
                                       float4* __restrict__ dst4,
                                       float* srow) {
    int tid = threadIdx.x;
    float4 v = src4[tid];                 // 1024 float4 = 32 rows x 128
    *(float4*)&srow[tid * 4] = v;
    __syncthreads();
    int tx = tid & 31, ty = tid >> 5;
    float acc[4][4];
#pragma unroll
    for (int i = 0; i < 4; i++)
#pragma unroll
        for (int j = 0; j < 4; j++) acc[i][j] = 0.f;
#pragma unroll 8
    for (int bb = 0; bb < 32; bb++) {
        float4 a = *(const float4*)&srow[bb * 128 + ty * 4];
        float4 b = *(const float4*)&srow[bb * 128 + tx * 4];
        float ra[4] = {a.x, a.y, a.z, a.w};
        float rb[4] = {b.x, b.y, b.z, b.w};
#pragma unroll
        for (int i = 0; i < 4; i++)
#pragma unroll
            for (int j = 0; j < 4; j++) acc[i][j] += ra[i] * rb[j];
    }
#pragma unroll
    for (int i = 0; i < 4; i++)
        dst4[(ty * 4 + i) * 32 + tx] =
            make_float4(acc[i][0], acc[i][1], acc[i][2], acc[i][3]);
}

// ==================================================================
// K1: Z-Gram partials (blocks 0-127) || class stats (blocks 128-143)
// ==================================================================
__global__ void __launch_bounds__(NTHR) k1_gram_stats(
        const float* __restrict__ z, const int* __restrict__ y) {
    __shared__ float sm[4096];
    const int blk = blockIdx.x;
    const int tid = threadIdx.x;
    const int lane = tid & 31, warp = tid >> 5;
    const float4* z4 = (const float4*)z;

    if (blk < 128) {
        gram32(&z4[blk * 1024], (float4*)&g_pp[blk * 16384], sm);
    } else if (blk < 144) {
        // warp-per-class stats via ballot scan
        int c = (blk - 128) * 32 + warp;
        float ax = 0.f, ay = 0.f, az = 0.f, aw = 0.f;
        int n = 0;
        for (int b0 = 0; b0 < Bn; b0 += 128) {
            int l0 = y[b0 + lane];
            int l1 = y[b0 + 32 + lane];
            int l2 = y[b0 + 64 + lane];
            int l3 = y[b0 + 96 + lane];
            unsigned m0 = __ballot_sync(0xffffffffu, l0 == c);
            unsigned m1 = __ballot_sync(0xffffffffu, l1 == c);
            unsigned m2 = __ballot_sync(0xffffffffu, l2 == c);
            unsigned m3 = __ballot_sync(0xffffffffu, l3 == c);
            n += __popc(m0) + __popc(m1) + __popc(m2) + __popc(m3);
            unsigned ms[4] = {m0, m1, m2, m3};
#pragma unroll
            for (int k = 0; k < 4; k++) {
                unsigned m = ms[k];
                int base = b0 + k * 32;
                while (m) {
                    int b = base + __ffs(m) - 1;
                    m &= m - 1u;
                    float4 zv = z4[b * 32 + lane];
                    ax += zv.x; ay += zv.y; az += zv.z; aw += zv.w;
                }
            }
        }
        float ce = (float)n + EPSF;
        float inv = 1.0f / ce;
        float4 m4 = make_float4(ax * inv, ay * inv, az * inv, aw * inv);
        ((float4*)g_mean)[c * 32 + lane] = m4;
        float sw = sqrtf((float)n + 2.0f * EPSF);
        ((float4*)g_u)[c * 32 + lane] =
            make_float4(m4.x * sw, m4.y * sw, m4.z * sw, m4.w * sw);
        if (lane == 0) g_lp[c] = logf(ce) - logf(TOTALF);
    }
}

// ==================================================================
// K2: U-Gram -> pooled (wide reduce) -> GJ inverse -> qbias
// ==================================================================
__global__ void __launch_bounds__(NTHR) k2_pool_inv() {
    __shared__ float sm[4096];
    const int blk = blockIdx.x;
    const int tid = threadIdx.x;
    const int lane = tid & 31, warp = tid >> 5;

    // ---- Phase A: U-Gram partials (blocks 0-15) ----
    if (blk < 16) {
        gram32(&((const float4*)g_u)[blk * 1024],
               (float4*)&g_pp[(128 + blk) * 16384], sm);
    }
    gbar();

    // ---- Phase B: pooled = (Zsum - Usum)/total + eps*I ----
    // 128 blocks x 128 elems, 8 threads/elem, 18 indep loads each
    if (blk < 128) {
        int idx = blk * 128 + (tid >> 3);
        int sub = tid & 7;
        float a[18];
#pragma unroll
        for (int i = 0; i < 18; i++) {
            int p = sub * 18 + i;
            float v = g_pp[p * 16384 + idx];
            a[i] = (p < 128) ? v : -v;
        }
        float s = 0.f;
#pragma unroll
        for (int i = 0; i < 18; i++) s += a[i];
        s += __shfl_xor_sync(0xffffffffu, s, 4);
        s += __shfl_xor_sync(0xffffffffu, s, 2);
        s += __shfl_xor_sync(0xffffffffu, s, 1);
        if (sub == 0) {
            int i = idx >> 7, j = idx & 127;
            g_pooled[idx] = s * (1.0f / TOTALF) + (i == j ? EPSF : 0.f);
        }
    }
    gbar();

    // ---- Phase C (block 0): in-place register Gauss-Jordan ----
    // No dynamic register indexing (pivot col via unrolled selects).
    if (blk == 0) {
        const int row = tid >> 3, grp = tid & 7;
        float r[16];
#pragma unroll
        for (int t = 0; t < 16; t += 4) {
            float4 v = *(const float4*)&g_pooled[row * 128 + grp * 16 + t];
            r[t] = v.x; r[t + 1] = v.y; r[t + 2] = v.z; r[t + 3] = v.w;
        }
        float* s_row2 = sm;            // 256
        float* s_f2   = sm + 256;      // 256
        float* s_piv2 = sm + 512;      // 2
#pragma unroll 1
        for (int k = 0; k < 128; k++) {
            const int p = k & 1;
            const int gk = k >> 4;
            const int kk = k & 15;
            if (grp == gk) {
                float cv = 0.f;
#pragma unroll
                for (int t = 0; t < 16; t++) if (t == kk) cv = r[t];
                if (row == k) s_piv2[p] = cv;
                else          s_f2[p * 128 + row] = cv;
            }
            __syncthreads();
            float pinv = 1.0f / s_piv2[p];
            if (row == k) {
#pragma unroll
                for (int t = 0; t < 16; t++) r[t] *= pinv;
                if (grp == gk) {
#pragma unroll
                    for (int t = 0; t < 16; t++) if (t == kk) r[t] = pinv;
                }
#pragma unroll
                for (int t = 0; t < 16; t++) s_row2[p * 128 + grp * 16 + t] = r[t];
            }
            __syncthreads();
            if (row != k) {
                float f = s_f2[p * 128 + row];
#pragma unroll
                for (int t = 0; t < 16; t++)
                    r[t] -= f * s_row2[p * 128 + grp * 16 + t];
                if (grp == gk) {
                    float nv = -f * pinv;
#pragma unroll
                    for (int t = 0; t < 16; t++) if (t == kk) r[t] = nv;
                }
            }
        }
        __syncthreads();
#pragma unroll
        for (int t = 0; t < 16; t += 4) {
            float4 v = make_float4(r[t], r[t + 1], r[t + 2], r[t + 3]);
            *(float4*)&g_prec[row * 128 + grp * 16 + t] = v;
        }
    }
    gbar();

    // ---- Phase D: qbias (blocks 0-15, warp per class) ----
    if (blk < 16) {
        int c = blk * 32 + warp;
        float4 m4 = ((const float4*)g_mean)[c * 32 + lane];
        float4 v = make_float4(0.f, 0.f, 0.f, 0.f);
        const float4* prec4 = (const float4*)g_prec;
#pragma unroll 4
        for (int d0 = 0; d0 < 128; d0 += 4) {
            int src = d0 >> 2;
            float a0 = __shfl_sync(0xffffffffu, m4.x, src);
            float a1 = __shfl_sync(0xffffffffu, m4.y, src);
            float a2 = __shfl_sync(0xffffffffu, m4.z, src);
            float a3 = __shfl_sync(0xffffffffu, m4.w, src);
            float4 p0 = prec4[(d0 + 0) * 32 + lane];
            float4 p1 = prec4[(d0 + 1) * 32 + lane];
            float4 p2 = prec4[(d0 + 2) * 32 + lane];
            float4 p3 = prec4[(d0 + 3) * 32 + lane];
            v.x += a0 * p0.x + a1 * p1.x + a2 * p2.x + a3 * p3.x;
            v.y += a0 * p0.y + a1 * p1.y + a2 * p2.y + a3 * p3.y;
            v.z += a0 * p0.z + a1 * p1.z + a2 * p2.z + a3 * p3.z;
            v.w += a0 * p0.w + a1 * p1.w + a2 * p2.w + a3 * p3.w;
        }
        float q = v.x * m4.x + v.y * m4.y + v.z * m4.z + v.w * m4.w;
#pragma unroll
        for (int o = 16; o; o >>= 1) q += __shfl_xor_sync(0xffffffffu, q, o);
        if (lane == 0) g_bias[c] = g_lp[c] - 0.5f * q;
    }
}

// ==================================================================
// K3: Pz + zPz -> out GEMM
// ==================================================================
__global__ void __launch_bounds__(NTHR) k3_score(
        const float* __restrict__ z, float* __restrict__ out) {
    __shared__ float sm[8704];
    const int blk = blockIdx.x;
    const int tid = threadIdx.x;
    const int lane = tid & 31;
    const float4* z4 = (const float4*)z;

    // ---- Phase A: Pz + zPz (blocks 0-127, 32 rows each) ----
    if (blk < 128) {
        int b0 = blk * 32;
        float* szf = sm;            // 32x128
        float* sP  = sm + 4096;     // 32x128
        float* swp = sm + 8192;     // 32x4
        *(float4*)&szf[tid * 4] = z4[b0 * 32 + tid];
        int j = tid & 127, rg = tid >> 7;
        float acc[4] = {0.f, 0.f, 0.f, 0.f};
        for (int d0 = 0; d0 < 128; d0 += 32) {
            __syncthreads();
            ((float4*)sP)[tid] = ((const float4*)g_prec)[d0 * 32 + tid];
            __syncthreads();
#pragma unroll 8
            for (int dd = 0; dd < 32; dd++) {
                float pv = sP[dd * 128 + j];
#pragma unroll
                for (int rr = 0; rr < 4; rr++)
                    acc[rr] += szf[(rg * 4 + rr) * 128 + d0 + dd] * pv;
            }
        }
#pragma unroll
        for (int rr = 0; rr < 4; rr++)
            g_Pz[(b0 + rg * 4 + rr) * 128 + j] = acc[rr];
        int jc = (tid >> 5) & 3;
#pragma unroll
        for (int rr = 0; rr < 4; rr++) {
            float s = acc[rr] * szf[(rg * 4 + rr) * 128 + j];
#pragma unroll
            for (int o = 16; o; o >>= 1) s += __shfl_xor_sync(0xffffffffu, s, o);
            if (lane == 0) swp[(rg * 4 + rr) * 4 + jc] = s;
        }
        __syncthreads();
        if (tid < 32)
            g_zPz[b0 + tid] = (swp[tid * 4 + 0] + swp[tid * 4 + 1]) +
                              (swp[tid * 4 + 2] + swp[tid * 4 + 3]);
    }
    gbar();

    // ---- Phase B: out = Pz @ mean^T + bias - 0.5 zPz ----
    if (blk < 128) {
        int by = blk >> 2, bx = blk & 3;   // 32 x 4 tiles of 128x128
        float* sA = sm;                    // [32][132] transposed Pz
        float* sB = sm + 32 * 132;         // [32][132] transposed mean
        int tx = tid & 31, ty = tid >> 5;
        float acc[4][4];
#pragma unroll
        for (int i = 0; i < 4; i++)
#pragma unroll
            for (int j = 0; j < 4; j++) acc[i][j] = 0.f;
        for (int d0 = 0; d0 < 128; d0 += 32) {
            __syncthreads();
#pragma unroll
            for (int e0 = 0; e0 < 4096; e0 += 1024) {
                int e = e0 + tid;
                int dd = e & 31, rr = e >> 5;
                sA[dd * 132 + rr] = g_Pz[(by * 128 + rr) * 128 + d0 + dd];
                sB[dd * 132 + rr] = g_mean[(bx * 128 + rr) * 128 + d0 + dd];
            }
            __syncthreads();
#pragma unroll 8
            for (int dd = 0; dd < 32; dd++) {
                float4 a = *(const float4*)&sA[dd * 132 + ty * 4];
                float4 b = *(const float4*)&sB[dd * 132 + tx * 4];
                float ra[4] = {a.x, a.y, a.z, a.w};
                float rb[4] = {b.x, b.y, b.z, b.w};
#pragma unroll
                for (int i = 0; i < 4; i++)
#pragma unroll
                    for (int j = 0; j < 4; j++) acc[i][j] += ra[i] * rb[j];
            }
        }
        float zr[4];
        float4 bc = *(const float4*)&g_bias[bx * 128 + tx * 4];
#pragma unroll
        for (int i = 0; i < 4; i++) zr[i] = g_zPz[by * 128 + ty * 4 + i];
        float bcv[4] = {bc.x, bc.y, bc.z, bc.w};
#pragma unroll
        for (int i = 0; i < 4; i++) {
            int row = by * 128 + ty * 4 + i;
            float4 o;
            o.x = acc[i][0] + bcv[0] - 0.5f * zr[i];
            o.y = acc[i][1] + bcv[1] - 0.5f * zr[i];
            o.z = acc[i][2] + bcv[2] - 0.5f * zr[i];
            o.w = acc[i][3] + bcv[3] - 0.5f * zr[i];
            *(float4*)&out[row * Cn + bx * 128 + tx * 4] = o;
        }
    }
}

// ------------------------------------------------------------------
extern "C" void kernel_launch(void* const* d_in, const int* in_sizes, int n_in,
                              void* d_out, int out_size) {
    const float* z;
    const int* y;
    if (in_sizes[0] == Bn * Dn) {
        z = (const float*)d_in[0];
        y = (const int*)d_in[1];
    } else {
        z = (const float*)d_in[1];
        y = (const int*)d_in[0];
    }
    k1_gram_stats<<<NBLK, NTHR>>>(z, y);
    k2_pool_inv<<<NBLK, NTHR>>>();
    k3_score<<<NBLK, NTHR>>>(z, (float*)d_out);
}